// round 6
// baseline (speedup 1.0000x reference)
#include <cuda_runtime.h>
#include <cstdint>

// Fused persistent PatchGram kernel: both layers in one launch.
// Per patch n, per layer (C channels, c_red=64, P=9):
//   fr[cr][p]  = mean over K=C/64 consecutive channels
//   sg[g][p]   = sum of 4 consecutive fr rows (output pooling folded)
//   out[n][layer][cr*16+g] = (1/(4*P)) * sum_p fr[cr][p] * sg[g][p]

__device__ __forceinline__ uint32_t smem_u32(const void* p) {
    return (uint32_t)__cvta_generic_to_shared(p);
}
__device__ __forceinline__ void mbar_init(uint32_t a, uint32_t cnt) {
    asm volatile("mbarrier.init.shared.b64 [%0], %1;" :: "r"(a), "r"(cnt) : "memory");
}
__device__ __forceinline__ void mbar_expect_tx(uint32_t a, uint32_t bytes) {
    asm volatile("mbarrier.arrive.expect_tx.shared.b64 _, [%0], %1;"
                 :: "r"(a), "r"(bytes) : "memory");
}
__device__ __forceinline__ void mbar_wait(uint32_t a, uint32_t phase) {
    asm volatile(
        "{\n\t"
        ".reg .pred p;\n\t"
        "WAIT_%=:\n\t"
        "mbarrier.try_wait.parity.acquire.cta.shared::cta.b64 p, [%0], %1, 0x989680;\n\t"
        "@p bra DONE_%=;\n\t"
        "bra WAIT_%=;\n\t"
        "DONE_%=:\n\t"
        "}"
        :: "r"(a), "r"(phase) : "memory");
}
__device__ __forceinline__ void bulk_g2s(uint32_t dst_smem, const void* src_gmem,
                                         uint32_t bytes, uint32_t mbar) {
    asm volatile(
        "cp.async.bulk.shared::cluster.global.mbarrier::complete_tx::bytes "
        "[%0], [%1], %2, [%3];"
        :: "r"(dst_smem), "l"(src_gmem), "r"(bytes), "r"(mbar) : "memory");
}

// Worker: processes patches [p_beg, p_end) of one layer with an S-stage ring.
template <int C, int S>
__device__ __forceinline__ void worker(const float* __restrict__ feat,
                                       float* __restrict__ out, int layer,
                                       int p_beg, int p_end,
                                       float* buf,                      // [S][NF]
                                       float (*fr)[12], float (*sg)[12],
                                       unsigned long long* mbar_s)
{
    constexpr int P  = 9;
    constexpr int K  = C / 64;
    constexpr int NF = C * P;
    constexpr uint32_t BYTES = NF * 4u;

    const int tid = threadIdx.x;
    const uint32_t bufa = smem_u32(buf);
    uint32_t mb[S];
#pragma unroll
    for (int i = 0; i < S; i++) mb[i] = smem_u32(&mbar_s[i]);

    if (tid == 0)
#pragma unroll
        for (int i = 0; i < S; i++) mbar_init(mb[i], 1);
    __syncthreads();

    const int cnt = p_end - p_beg;

    // Prologue: fill the ring.
    if (tid == 0) {
#pragma unroll
        for (int i = 0; i < S; i++)
            if (i < cnt) {
                mbar_expect_tx(mb[i], BYTES);
                bulk_g2s(bufa + (uint32_t)i * BYTES,
                         feat + (size_t)(p_beg + i) * NF, BYTES, mb[i]);
            }
    }

    int s = 0, phase = 0;
    for (int jj = 0; jj < cnt; jj++) {
        mbar_wait(mb[s], phase);

        // ---- fused reduce + output-pool fold: 144 threads, 4 fr rows each ----
        if (tid < 144) {
            const int g = tid / 9;
            const int p = tid - g * 9;
            const float* b = buf + s * NF + (g * 4 * K) * P + p;
            float sgv = 0.0f;
#pragma unroll
            for (int c4 = 0; c4 < 4; c4++) {
                float acc = 0.0f;
#pragma unroll
                for (int j = 0; j < K; j++)
                    acc += b[(c4 * K + j) * P];
                fr[4 * g + c4][p] = acc * (1.0f / (float)K);
                sgv += acc;
            }
            sg[g][p] = sgv * (1.0f / (float)K);
        }
        __syncthreads();   // fr/sg ready; all readers of buf[s] done.

        // Earliest legal point to re-issue this stage for patch jj+S.
        if (tid == 0 && jj + S < cnt) {
            mbar_expect_tx(mb[s], BYTES);
            bulk_g2s(bufa + (uint32_t)s * BYTES,
                     feat + (size_t)(p_beg + jj + S) * NF, BYTES, mb[s]);
        }

        // ---- epilogue: thread -> (cr, quad), one float4 store ----
        {
            constexpr float scale = 1.0f / (4.0f * (float)P);
            const int cr = tid >> 2;
            const int q  = tid & 3;
            float frr[9];
#pragma unroll
            for (int p = 0; p < 9; p++) frr[p] = fr[cr][p];

            float4 r;
            float* rv = &r.x;
#pragma unroll
            for (int m = 0; m < 4; m++) {
                const int g = q * 4 + m;
                float acc = 0.0f;
#pragma unroll
                for (int p = 0; p < 9; p++)
                    acc += frr[p] * sg[g][p];
                rv[m] = acc * scale;
            }
            float4* o = reinterpret_cast<float4*>(
                out + (size_t)(p_beg + jj) * 2048 + (size_t)layer * 1024 + cr * 16 + q * 4);
            __stcs(o, r);
        }
        __syncthreads();   // fr/sg consumed before next iteration overwrites.

        if (++s == S) { s = 0; phase ^= 1; }
    }
}

__global__ __launch_bounds__(256)
void fused_gram_kernel(const float* __restrict__ feat0,
                       const float* __restrict__ feat1,
                       float* __restrict__ out, int N, int B1, int B0)
{
    extern __shared__ float buf[];                  // 108 KB ring
    __shared__ float fr[64][12];
    __shared__ float sg[16][12];
    __shared__ alignas(8) unsigned long long mbar_s[6];

    const int b = blockIdx.x;
    if (b < B1) {
        // layer 1: C=1024, 3 stages x 36 KB
        int beg = (int)((long long)b * N / B1);
        int end = (int)((long long)(b + 1) * N / B1);
        worker<1024, 3>(feat1, out, 1, beg, end, buf, fr, sg, mbar_s);
    } else {
        // layer 0: C=512, 6 stages x 18 KB
        int c = b - B1;
        int beg = (int)((long long)c * N / B0);
        int end = (int)((long long)(c + 1) * N / B0);
        worker<512, 6>(feat0, out, 0, beg, end, buf, fr, sg, mbar_s);
    }
}

extern "C" void kernel_launch(void* const* d_in, const int* in_sizes, int n_in,
                              void* d_out, int out_size)
{
    const float* feat0 = (const float*)d_in[0];   // [N, 512, 3, 3]
    const float* feat1 = (const float*)d_in[1];   // [N, 1024, 3, 3]
    float* out = (float*)d_out;                   // [N, 2, 1024]

    const int N = in_sizes[0] / (512 * 9);

    constexpr int SMEM = 3 * 1024 * 9 * 4;        // 108 KB ring (== 6 * 18 KB)
    cudaFuncSetAttribute(fused_gram_kernel,
                         cudaFuncAttributeMaxDynamicSharedMemorySize, SMEM);

    const int GRID = 296;                          // 2 persistent CTAs / SM
    const int B1 = (GRID * 2) / 3;                 // layer1 share (~2/3 of traffic)
    const int B0 = GRID - B1;

    fused_gram_kernel<<<GRID, 256, SMEM>>>(feat0, feat1, out, N, B1, B0);
}

// round 7
// speedup vs baseline: 1.7175x; 1.7175x over previous
#include <cuda_runtime.h>
#include <cstdint>

// Fused persistent PatchGram kernel (R6): both layers one launch, strided
// patch assignment, 72 KB rings (2 CTAs/SM), low-conflict reduce.
// Per patch n, per layer (C channels, c_red=64, P=9):
//   fr[cr][p]  = mean over K=C/64 consecutive channels
//   sg[g][p]   = sum of 4 consecutive fr rows
//   out[n][layer][cr*16+g] = (1/(4*P)) * sum_p fr[cr][p] * sg[g][p]

__device__ __forceinline__ uint32_t smem_u32(const void* p) {
    return (uint32_t)__cvta_generic_to_shared(p);
}
__device__ __forceinline__ void mbar_init(uint32_t a, uint32_t cnt) {
    asm volatile("mbarrier.init.shared.b64 [%0], %1;" :: "r"(a), "r"(cnt) : "memory");
}
__device__ __forceinline__ void mbar_expect_tx(uint32_t a, uint32_t bytes) {
    asm volatile("mbarrier.arrive.expect_tx.shared.b64 _, [%0], %1;"
                 :: "r"(a), "r"(bytes) : "memory");
}
__device__ __forceinline__ void mbar_wait(uint32_t a, uint32_t phase) {
    asm volatile(
        "{\n\t"
        ".reg .pred p;\n\t"
        "WAIT_%=:\n\t"
        "mbarrier.try_wait.parity.acquire.cta.shared::cta.b64 p, [%0], %1, 0x989680;\n\t"
        "@p bra DONE_%=;\n\t"
        "bra WAIT_%=;\n\t"
        "DONE_%=:\n\t"
        "}"
        :: "r"(a), "r"(phase) : "memory");
}
__device__ __forceinline__ void bulk_g2s(uint32_t dst_smem, const void* src_gmem,
                                         uint32_t bytes, uint32_t mbar) {
    asm volatile(
        "cp.async.bulk.shared::cluster.global.mbarrier::complete_tx::bytes "
        "[%0], [%1], %2, [%3];"
        :: "r"(dst_smem), "l"(src_gmem), "r"(bytes), "r"(mbar) : "memory");
}

// Worker: processes patches j0, j0+stride, ... (<N) with an S-stage ring.
template <int C, int S>
__device__ __forceinline__ void worker(const float* __restrict__ feat,
                                       float* __restrict__ out, int layer,
                                       int j0, int stride, int N,
                                       float* buf,                   // [S][NF]
                                       float (*fr)[12], float (*sg)[12],
                                       unsigned long long* mbar_s)
{
    constexpr int P  = 9;
    constexpr int K  = C / 64;
    constexpr int NF = C * P;
    constexpr uint32_t BYTES = NF * 4u;

    const int tid = threadIdx.x;
    const uint32_t bufa = smem_u32(buf);
    uint32_t mb[S];
#pragma unroll
    for (int i = 0; i < S; i++) mb[i] = smem_u32(&mbar_s[i]);

    if (tid == 0)
#pragma unroll
        for (int i = 0; i < S; i++) mbar_init(mb[i], 1);
    __syncthreads();

    // Prologue: fill the ring.
    if (tid == 0) {
#pragma unroll
        for (int i = 0; i < S; i++) {
            const int jt = j0 + i * stride;
            if (jt < N) {
                mbar_expect_tx(mb[i], BYTES);
                bulk_g2s(bufa + (uint32_t)i * BYTES,
                         feat + (size_t)jt * NF, BYTES, mb[i]);
            }
        }
    }

    int s = 0, phase = 0;
    for (int j = j0; j < N; j += stride) {
        mbar_wait(mb[s], phase);

        const float* b0 = buf + s * NF;

        // ---- channel-group reduction (256 threads, low-conflict mapping) ----
        for (int i = tid; i < 64 * P; i += 256) {
            const int cr = i / P;
            const int p  = i - cr * P;
            const float* b = b0 + (cr * K) * P + p;
            float acc = 0.0f;
#pragma unroll
            for (int q = 0; q < K; q++)
                acc += b[q * P];
            fr[cr][p] = acc * (1.0f / (float)K);
        }
        __syncthreads();   // fr ready; all readers of buf[s] done.

        // Earliest legal point to re-issue this stage for patch j + S*stride.
        if (tid == 0 && j + S * stride < N) {
            mbar_expect_tx(mb[s], BYTES);
            bulk_g2s(bufa + (uint32_t)s * BYTES,
                     feat + (size_t)(j + S * stride) * NF, BYTES, mb[s]);
        }

        // ---- fold output pooling ----
        if (tid < 16 * P) {
            const int g = tid / P;
            const int p = tid - g * P;
            sg[g][p] = fr[4 * g + 0][p] + fr[4 * g + 1][p]
                     + fr[4 * g + 2][p] + fr[4 * g + 3][p];
        }
        __syncthreads();

        // ---- epilogue: thread -> (cr, quad), one float4 streaming store ----
        {
            constexpr float scale = 1.0f / (4.0f * (float)P);
            const int cr = tid >> 2;
            const int q  = tid & 3;
            float frr[9];
#pragma unroll
            for (int p = 0; p < 9; p++) frr[p] = fr[cr][p];

            float4 r;
            float* rv = &r.x;
#pragma unroll
            for (int m = 0; m < 4; m++) {
                const int g = q * 4 + m;
                float acc = 0.0f;
#pragma unroll
                for (int p = 0; p < 9; p++)
                    acc += frr[p] * sg[g][p];
                rv[m] = acc * scale;
            }
            float4* o = reinterpret_cast<float4*>(
                out + (size_t)j * 2048 + (size_t)layer * 1024 + cr * 16 + q * 4);
            __stcs(o, r);
        }
        __syncthreads();   // fr/sg consumed before next iteration overwrites.

        if (++s == S) { s = 0; phase ^= 1; }
    }
}

__global__ __launch_bounds__(256)
void fused_gram_kernel(const float* __restrict__ feat0,
                       const float* __restrict__ feat1,
                       float* __restrict__ out, int N, int B1, int B0)
{
    extern __shared__ float buf[];                  // 72 KB ring
    __shared__ float fr[64][12];
    __shared__ float sg[16][12];
    __shared__ alignas(8) unsigned long long mbar_s[4];

    const int b = blockIdx.x;
    if (b < B1) {
        // layer 1: C=1024, 2 stages x 36 KB
        worker<1024, 2>(feat1, out, 1, b, B1, N, buf, fr, sg, mbar_s);
    } else {
        // layer 0: C=512, 4 stages x 18 KB
        worker<512, 4>(feat0, out, 0, b - B1, B0, N, buf, fr, sg, mbar_s);
    }
}

extern "C" void kernel_launch(void* const* d_in, const int* in_sizes, int n_in,
                              void* d_out, int out_size)
{
    const float* feat0 = (const float*)d_in[0];   // [N, 512, 3, 3]
    const float* feat1 = (const float*)d_in[1];   // [N, 1024, 3, 3]
    float* out = (float*)d_out;                   // [N, 2, 1024]

    const int N = in_sizes[0] / (512 * 9);

    constexpr int SMEM = 2 * 1024 * 9 * 4;        // 72 KB ring (== 4 * 18 KB)
    cudaFuncSetAttribute(fused_gram_kernel,
                         cudaFuncAttributeMaxDynamicSharedMemorySize, SMEM);

    const int GRID = 296;                          // 2 persistent CTAs / SM
    const int B1 = (GRID * 2) / 3;                 // layer1 share (~2/3 of traffic)
    const int B0 = GRID - B1;

    fused_gram_kernel<<<GRID, 256, SMEM>>>(feat0, feat1, out, N, B1, B0);
}

// round 11
// speedup vs baseline: 2.0585x; 1.1986x over previous
#include <cuda_runtime.h>
#include <cstdint>

// R8: fused persistent PatchGram, uniform 36KB work units.
// Every CTA: strided share of layer1 patches (36KB each), then strided share
// of layer0 patch-PAIRS (2 contiguous patches = 36KB), through one S=2 ring.
//   fr[cr][p]  = mean over K=C/64 consecutive channels
//   sg[g][p]   = sum of 4 consecutive fr rows
//   out[n][layer][cr*16+g] = (1/(4*9)) * sum_p fr[cr][p] * sg[g][p]

__device__ __forceinline__ uint32_t smem_u32(const void* p) {
    return (uint32_t)__cvta_generic_to_shared(p);
}
__device__ __forceinline__ void mbar_init(uint32_t a, uint32_t cnt) {
    asm volatile("mbarrier.init.shared.b64 [%0], %1;" :: "r"(a), "r"(cnt) : "memory");
}
__device__ __forceinline__ void mbar_expect_tx(uint32_t a, uint32_t bytes) {
    asm volatile("mbarrier.arrive.expect_tx.shared.b64 _, [%0], %1;"
                 :: "r"(a), "r"(bytes) : "memory");
}
__device__ __forceinline__ void mbar_wait(uint32_t a, uint32_t phase) {
    asm volatile(
        "{\n\t"
        ".reg .pred p;\n\t"
        "WAIT_%=:\n\t"
        "mbarrier.try_wait.parity.acquire.cta.shared::cta.b64 p, [%0], %1, 0x989680;\n\t"
        "@p bra DONE_%=;\n\t"
        "bra WAIT_%=;\n\t"
        "DONE_%=:\n\t"
        "}"
        :: "r"(a), "r"(phase) : "memory");
}
__device__ __forceinline__ void bulk_g2s(uint32_t dst_smem, const void* src_gmem,
                                         uint32_t bytes, uint32_t mbar) {
    asm volatile(
        "cp.async.bulk.shared::cluster.global.mbarrier::complete_tx::bytes "
        "[%0], [%1], %2, [%3];"
        :: "r"(dst_smem), "l"(src_gmem), "r"(bytes), "r"(mbar) : "memory");
}

__global__ __launch_bounds__(256)
void fused_gram_kernel(const float* __restrict__ feat0,
                       const float* __restrict__ feat1,
                       float* __restrict__ out, int N)
{
    constexpr int P   = 9;
    constexpr int NFU = 9216;                 // floats per 36KB unit
    constexpr uint32_t BYTES = NFU * 4u;      // uniform stage size
    constexpr int S = 2;

    extern __shared__ float buf[];            // [S][NFU] = 72 KB
    __shared__ float fr[2][64][12];           // [half][cr][p]
    __shared__ float sg[2][16][12];
    __shared__ alignas(8) unsigned long long mbar_s[S];

    const int tid = threadIdx.x;
    const int b   = blockIdx.x;
    const int G   = gridDim.x;

    const int NP   = N / 2;                          // layer0 pairs
    const int n1   = (N  > b) ? (N  - b + G - 1) / G : 0;   // layer1 iters
    const int n0p  = (NP > b) ? (NP - b + G - 1) / G : 0;   // pair iters
    const int total = n1 + n0p;

    const uint32_t bufa = smem_u32(buf);
    uint32_t mb[S];
#pragma unroll
    for (int i = 0; i < S; i++) mb[i] = smem_u32(&mbar_s[i]);

    if (tid == 0) { mbar_init(mb[0], 1); mbar_init(mb[1], 1); }
    __syncthreads();

    // iteration t -> gmem source (uniform 36KB units)
    auto src_of = [&](int t) -> const float* {
        if (t < n1) return feat1 + (size_t)(b + t * G) * NFU;
        return feat0 + (size_t)(b + (t - n1) * G) * NFU;
    };

    // Prologue: fill ring.
    if (tid == 0) {
#pragma unroll
        for (int i = 0; i < S; i++)
            if (i < total) {
                mbar_expect_tx(mb[i], BYTES);
                bulk_g2s(bufa + (uint32_t)i * BYTES, src_of(i), BYTES, mb[i]);
            }
    }

    constexpr float scale = 1.0f / (4.0f * (float)P);
    int s = 0, phase = 0;

    for (int t = 0; t < total; t++) {
        mbar_wait(mb[s], phase);
        const float* b0 = buf + s * NFU;
        const bool isL1 = (t < n1);

        // ---- reduce: fr (low-conflict cr-major mapping) ----
        if (isL1) {
            // one layer1 patch: K=16, 576 outputs into fr[0]
            for (int i = tid; i < 576; i += 256) {
                const int cr = i / 9;
                const int p  = i - cr * 9;
                const float* bp = b0 + (cr * 16) * 9 + p;
                float acc = 0.0f;
#pragma unroll
                for (int q = 0; q < 16; q++) acc += bp[q * 9];
                fr[0][cr][p] = acc * (1.0f / 16.0f);
            }
        } else {
            // layer0 pair: K=8, 2 x 576 outputs into fr[0], fr[1]
            for (int i = tid; i < 1152; i += 256) {
                const int h  = i >> 9 & 1 ? 0 : 0;   // placeholder, recomputed below
                const int hh = i / 576;
                const int r  = i - hh * 576;
                const int cr = r / 9;
                const int p  = r - cr * 9;
                const float* bp = b0 + hh * 4608 + (cr * 8) * 9 + p;
                float acc = 0.0f;
#pragma unroll
                for (int q = 0; q < 8; q++) acc += bp[q * 9];
                fr[hh][cr][p] = acc * (1.0f / 8.0f);
                (void)h;
            }
        }
        __syncthreads();   // fr ready; buf[s] fully consumed.

        // Re-issue this stage for iteration t+S (earliest legal point).
        if (tid == 0 && t + S < total) {
            mbar_expect_tx(mb[s], BYTES);
            bulk_g2s(bufa + (uint32_t)s * BYTES, src_of(t + S), BYTES, mb[s]);
        }

        // ---- fold output pooling ----
        {
            const int lim = isL1 ? 144 : 288;
            for (int i = tid; i < lim; i += 256) {
                const int hh = i / 144;
                const int r  = i - hh * 144;
                const int g  = r / 9;
                const int p  = r - g * 9;
                sg[hh][g][p] = fr[hh][4 * g + 0][p] + fr[hh][4 * g + 1][p]
                             + fr[hh][4 * g + 2][p] + fr[hh][4 * g + 3][p];
            }
        }
        __syncthreads();

        // ---- epilogue: per half, thread -> (cr, quad), one float4 store ----
        const int nh = isL1 ? 1 : 2;
        for (int hh = 0; hh < nh; hh++) {
            const int cr = tid >> 2;
            const int q  = tid & 3;
            float frr[9];
#pragma unroll
            for (int p = 0; p < 9; p++) frr[p] = fr[hh][cr][p];

            float4 r4;
            float* rv = &r4.x;
#pragma unroll
            for (int m = 0; m < 4; m++) {
                const int g = q * 4 + m;
                float acc = 0.0f;
#pragma unroll
                for (int p = 0; p < 9; p++)
                    acc += frr[p] * sg[hh][g][p];
                rv[m] = acc * scale;
            }

            size_t obase;
            if (isL1) {
                const int j = b + t * G;                 // layer1 patch
                obase = (size_t)j * 2048 + 1024;
            } else {
                const int qp = b + (t - n1) * G;         // layer0 pair
                obase = (size_t)(2 * qp + hh) * 2048;
            }
            __stcs(reinterpret_cast<float4*>(out + obase + cr * 16 + q * 4), r4);
        }
        __syncthreads();   // fr/sg consumed before next overwrite.

        if (++s == S) { s = 0; phase ^= 1; }
    }
}

extern "C" void kernel_launch(void* const* d_in, const int* in_sizes, int n_in,
                              void* d_out, int out_size)
{
    const float* feat0 = (const float*)d_in[0];   // [N, 512, 3, 3]
    const float* feat1 = (const float*)d_in[1];   // [N, 1024, 3, 3]
    float* out = (float*)d_out;                   // [N, 2, 1024]

    const int N = in_sizes[0] / (512 * 9);

    constexpr int SMEM = 2 * 9216 * 4;            // 72 KB ring
    cudaFuncSetAttribute(fused_gram_kernel,
                         cudaFuncAttributeMaxDynamicSharedMemorySize, SMEM);

    const int GRID = 296;                          // 2 persistent CTAs / SM
    fused_gram_kernel<<<GRID, 256, SMEM>>>(feat0, feat1, out, N);
}